// round 3
// baseline (speedup 1.0000x reference)
#include <cuda_runtime.h>

#define Bn 64
#define Cn 8
#define Nn 2048
#define Tn 64
#define PLANE4 (Nn * Tn / 4)   // 32768 float4 per (b,c) plane

// Scratch (no allocations allowed)
__device__ float g_k[Bn * Cn * Tn];     // 32768 floats
__device__ float g_att[Bn * Cn * Cn];   // 4096 floats

// ---------------------------------------------------------------------------
// Kernel 1: k[b,c,t] = sum_i alpha[i] * x[b,c,i,t]
// grid = B*C (512 blocks), 256 threads: 16 t-lanes (float4) x 16 i-rows
// ---------------------------------------------------------------------------
__global__ void k_reduce(const float* __restrict__ x,
                         const float* __restrict__ alpha) {
    int bc = blockIdx.x;                               // 0..511
    const float4* __restrict__ xp =
        (const float4*)x + (size_t)bc * PLANE4;
    int tid  = threadIdx.x;
    int lane = tid & 15;                               // t4 index (4 t's each)
    int row  = tid >> 4;                               // i-row group (16)

    float4 acc = make_float4(0.f, 0.f, 0.f, 0.f);
    #pragma unroll 4
    for (int i = row; i < Nn; i += 16) {
        float a  = __ldg(alpha + i);
        float4 v = xp[i * 16 + lane];                  // 16 float4 per i-row
        acc.x += a * v.x; acc.y += a * v.y;
        acc.z += a * v.z; acc.w += a * v.w;
    }

    __shared__ float4 s[16][16];
    s[row][lane] = acc;
    __syncthreads();
    for (int str = 8; str >= 1; str >>= 1) {
        if (row < str) {
            float4 o = s[row + str][lane];
            float4 m = s[row][lane];
            m.x += o.x; m.y += o.y; m.z += o.z; m.w += o.w;
            s[row][lane] = m;
        }
        __syncthreads();
    }
    if (row == 0) {
        ((float4*)(g_k + bc * Tn))[lane] = s[0][lane];
    }
}

// ---------------------------------------------------------------------------
// Kernel 2: scores[b,c,d] = sum_{t,s} k[b,c,t] Wc[t,s] k[b,d,s]; softmax over d
// grid = B (64 blocks), 64 threads
// ---------------------------------------------------------------------------
__global__ void k_scores(const float* __restrict__ Wc) {
    int b   = blockIdx.x;
    int tid = threadIdx.x;                             // 0..63

    __shared__ float ks[Cn][Tn];                       // k[b]
    __shared__ float kW[Cn][Tn];                       // k[b] @ Wc
    __shared__ float sc[Cn][Cn];

    for (int idx = tid; idx < Cn * Tn; idx += 64)
        ks[idx / Tn][idx % Tn] = g_k[b * Cn * Tn + idx];
    __syncthreads();

    // thread tid == column s; kW[c][s] = sum_t ks[c][t] * Wc[t,s]
    int s = tid;
    #pragma unroll
    for (int c = 0; c < Cn; c++) {
        float acc = 0.f;
        #pragma unroll 8
        for (int t = 0; t < Tn; t++)
            acc += ks[c][t] * __ldg(Wc + t * Tn + s);
        kW[c][s] = acc;
    }
    __syncthreads();

    int c = tid >> 3, d = tid & 7;
    float sco = 0.f;
    #pragma unroll 8
    for (int ss = 0; ss < Tn; ss++)
        sco += kW[c][ss] * ks[d][ss];
    sc[c][d] = sco;
    __syncthreads();

    float m = -1e30f;
    #pragma unroll
    for (int j = 0; j < Cn; j++) m = fmaxf(m, sc[c][j]);
    float den = 0.f;
    #pragma unroll
    for (int j = 0; j < Cn; j++) den += expf(sc[c][j] - m);
    g_att[b * Cn * Cn + tid] = expf(sco - m) / den;
}

// ---------------------------------------------------------------------------
// Kernel 3: out[b,c,n,t] = sum_d att[b,c,d] * x[b,d,n,t]
// grid = B * 128 blocks, 256 threads; each thread mixes one float4 position
// across all 8 channels (8 loads in flight -> MLP=8, fully coalesced)
// ---------------------------------------------------------------------------
__global__ void k_agg(const float* __restrict__ x,
                      float* __restrict__ out) {
    int b  = blockIdx.x >> 7;                          // /128
    int pb = blockIdx.x & 127;
    int p  = pb * 256 + threadIdx.x;                   // float4 pos in plane

    __shared__ float att[Cn * Cn];
    if (threadIdx.x < Cn * Cn)
        att[threadIdx.x] = g_att[b * Cn * Cn + threadIdx.x];
    __syncthreads();

    const float4* __restrict__ xp =
        (const float4*)x + (size_t)b * Cn * PLANE4 + p;
    float4* __restrict__ op =
        (float4*)out + (size_t)b * Cn * PLANE4 + p;

    float4 xv[Cn];
    #pragma unroll
    for (int d = 0; d < Cn; d++)
        xv[d] = xp[(size_t)d * PLANE4];

    #pragma unroll
    for (int c = 0; c < Cn; c++) {
        float4 acc = make_float4(0.f, 0.f, 0.f, 0.f);
        #pragma unroll
        for (int d = 0; d < Cn; d++) {
            float a = att[c * Cn + d];
            acc.x += a * xv[d].x; acc.y += a * xv[d].y;
            acc.z += a * xv[d].z; acc.w += a * xv[d].w;
        }
        op[(size_t)c * PLANE4] = acc;
    }
}

// ---------------------------------------------------------------------------
extern "C" void kernel_launch(void* const* d_in, const int* in_sizes, int n_in,
                              void* d_out, int out_size) {
    const float* x     = (const float*)d_in[0];
    const float* Wc    = (const float*)d_in[1];
    const float* alpha = (const float*)d_in[2];
    float* out         = (float*)d_out;

    k_reduce<<<Bn * Cn, 256>>>(x, alpha);
    k_scores<<<Bn, 64>>>(Wc);
    k_agg<<<Bn * 128, 256>>>(x, out);
}

// round 8
// speedup vs baseline: 1.0325x; 1.0325x over previous
#include <cuda_runtime.h>

#define Bn 64
#define Cn 8
#define Nn 2048
#define Tn 64
#define CH 8                    // i-chunks per (b,c) plane in k_reduce
#define PLANE4 (Nn * Tn / 4)    // 32768 float4 per (b,c) plane

// Scratch (no allocations allowed)
__device__ float g_kp[Bn * Cn * CH * Tn];  // partial k sums, 256 K floats = 1 MB
__device__ float g_att[Bn * Cn * Cn];      // 4096 floats

// ---------------------------------------------------------------------------
// Kernel 1: partial k: g_kp[bc][ch][t] = sum_{i in chunk ch} alpha[i]*x[b,c,i,t]
// grid = B*C*CH = 4096 blocks, 256 threads: 16 t4-lanes x 16 i-rows.
// Each block covers 256 i-rows -> 16 iterations/thread, unroll 8 (MLP=8).
// ---------------------------------------------------------------------------
__global__ void __launch_bounds__(256) k_reduce(const float* __restrict__ x,
                                                const float* __restrict__ alpha) {
    int blk = blockIdx.x;                  // 0..4095
    int bc  = blk >> 3;                    // (b,c) plane
    int ch  = blk & (CH - 1);
    int i0  = ch * (Nn / CH);              // 256-row chunk base

    const float4* __restrict__ xp =
        (const float4*)x + (size_t)bc * PLANE4 + (size_t)i0 * (Tn / 4);
    int tid  = threadIdx.x;
    int lane = tid & 15;                   // t4 index
    int row  = tid >> 4;                   // i-row group (16)

    float4 acc = make_float4(0.f, 0.f, 0.f, 0.f);
    #pragma unroll 8
    for (int it = 0; it < (Nn / CH) / 16; it++) {      // 16 iters
        int i    = it * 16 + row;
        float a  = __ldg(alpha + i0 + i);
        float4 v = __ldcs(xp + i * (Tn / 4) + lane);   // streaming: no L2 reuse
        acc.x += a * v.x; acc.y += a * v.y;
        acc.z += a * v.z; acc.w += a * v.w;
    }

    __shared__ float4 s[16][16];
    s[row][lane] = acc;
    __syncthreads();
    for (int str = 8; str >= 1; str >>= 1) {
        if (row < str) {
            float4 o = s[row + str][lane];
            float4 m = s[row][lane];
            m.x += o.x; m.y += o.y; m.z += o.z; m.w += o.w;
            s[row][lane] = m;
        }
        __syncthreads();
    }
    if (row == 0) {
        ((float4*)(g_kp + (size_t)blk * Tn))[lane] = s[0][lane];
    }
}

// ---------------------------------------------------------------------------
// Kernel 2: reduce partials -> k[b]; scores = k Wc k^T; softmax -> g_att
// grid = B (64 blocks), 64 threads
// ---------------------------------------------------------------------------
__global__ void k_scores(const float* __restrict__ Wc) {
    int b   = blockIdx.x;
    int tid = threadIdx.x;                             // 0..63

    __shared__ float ks[Cn][Tn];
    __shared__ float kW[Cn][Tn];
    __shared__ float sc[Cn][Cn];

    // sum the CH partial chunks
    for (int idx = tid; idx < Cn * Tn; idx += 64) {
        int c = idx / Tn, t = idx % Tn;
        const float* p = g_kp + (((size_t)(b * Cn + c)) * CH) * Tn + t;
        float acc = 0.f;
        #pragma unroll
        for (int h = 0; h < CH; h++) acc += p[h * Tn];
        ks[c][t] = acc;
    }
    __syncthreads();

    // kW[c][s] = sum_t ks[c][t] * Wc[t,s]; thread tid == column s
    int s = tid;
    #pragma unroll
    for (int c = 0; c < Cn; c++) {
        float acc = 0.f;
        #pragma unroll 8
        for (int t = 0; t < Tn; t++)
            acc += ks[c][t] * __ldg(Wc + t * Tn + s);
        kW[c][s] = acc;
    }
    __syncthreads();

    int c = tid >> 3, d = tid & 7;
    float sco = 0.f;
    #pragma unroll 8
    for (int ss = 0; ss < Tn; ss++)
        sco += kW[c][ss] * ks[d][ss];
    sc[c][d] = sco;
    __syncthreads();

    float m = -1e30f;
    #pragma unroll
    for (int j = 0; j < Cn; j++) m = fmaxf(m, sc[c][j]);
    float den = 0.f;
    #pragma unroll
    for (int j = 0; j < Cn; j++) den += expf(sc[c][j] - m);
    g_att[b * Cn * Cn + tid] = expf(sco - m) / den;
}

// ---------------------------------------------------------------------------
// Kernel 3: out[b,c,n,t] = sum_d att[b,c,d] * x[b,d,n,t]
// grid = B*128 blocks, 256 threads; thread mixes one float4 across 8 channels.
// Streaming loads + streaming stores (no reuse either way).
// ---------------------------------------------------------------------------
__global__ void __launch_bounds__(256) k_agg(const float* __restrict__ x,
                                             float* __restrict__ out) {
    int b  = blockIdx.x >> 7;
    int pb = blockIdx.x & 127;
    int p  = pb * 256 + threadIdx.x;                   // float4 pos in plane

    __shared__ float att[Cn * Cn];
    if (threadIdx.x < Cn * Cn)
        att[threadIdx.x] = g_att[b * Cn * Cn + threadIdx.x];
    __syncthreads();

    const float4* __restrict__ xp =
        (const float4*)x + (size_t)b * Cn * PLANE4 + p;
    float4* __restrict__ op =
        (float4*)out + (size_t)b * Cn * PLANE4 + p;

    float4 xv[Cn];
    #pragma unroll
    for (int d = 0; d < Cn; d++)
        xv[d] = __ldcs(xp + (size_t)d * PLANE4);

    #pragma unroll
    for (int c = 0; c < Cn; c++) {
        float4 acc = make_float4(0.f, 0.f, 0.f, 0.f);
        #pragma unroll
        for (int d = 0; d < Cn; d++) {
            float a = att[c * Cn + d];
            acc.x += a * xv[d].x; acc.y += a * xv[d].y;
            acc.z += a * xv[d].z; acc.w += a * xv[d].w;
        }
        __stcs(op + (size_t)c * PLANE4, acc);
    }
}

// ---------------------------------------------------------------------------
extern "C" void kernel_launch(void* const* d_in, const int* in_sizes, int n_in,
                              void* d_out, int out_size) {
    const float* x     = (const float*)d_in[0];
    const float* Wc    = (const float*)d_in[1];
    const float* alpha = (const float*)d_in[2];
    float* out         = (float*)d_out;

    k_reduce<<<Bn * Cn * CH, 256>>>(x, alpha);
    k_scores<<<Bn, 64>>>(Wc);
    k_agg<<<Bn * 128, 256>>>(x, out);
}

// round 9
// speedup vs baseline: 1.0352x; 1.0026x over previous
#include <cuda_runtime.h>

#define Bn 64
#define Cn 8
#define Nn 2048
#define Tn 64
#define CH 8                    // i-chunks per (b,c) plane in k_reduce
#define PLANE4 (Nn * Tn / 4)    // 32768 float4 per (b,c) plane

// Scratch (no allocations allowed)
__device__ float g_kp[Bn * Cn * CH * Tn];  // partial k sums, 1 MB
__device__ float g_att[Bn * Cn * Cn];      // 4096 floats

// ---------------------------------------------------------------------------
// Kernel 1: partial k: g_kp[bc][ch][t] = sum_{i in chunk ch} alpha[i]*x[b,c,i,t]
// grid = B*C*CH = 4096 blocks, 256 threads: 16 t4-lanes x 16 i-rows.
// Reads ascending over x with __ldcg so the tail of x is L2-resident at exit.
// ---------------------------------------------------------------------------
__global__ void __launch_bounds__(256) k_reduce(const float* __restrict__ x,
                                                const float* __restrict__ alpha) {
    int blk = blockIdx.x;                  // 0..4095
    int bc  = blk >> 3;                    // (b,c) plane, ascending
    int ch  = blk & (CH - 1);
    int i0  = ch * (Nn / CH);              // 256-row chunk base

    const float4* __restrict__ xp =
        (const float4*)x + (size_t)bc * PLANE4 + (size_t)i0 * (Tn / 4);
    int tid  = threadIdx.x;
    int lane = tid & 15;                   // t4 index
    int row  = tid >> 4;                   // i-row group (16)

    float4 acc = make_float4(0.f, 0.f, 0.f, 0.f);
    #pragma unroll 8
    for (int it = 0; it < (Nn / CH) / 16; it++) {      // 16 iters
        int i    = it * 16 + row;
        float a  = __ldg(alpha + i0 + i);
        float4 v = __ldcg(xp + i * (Tn / 4) + lane);   // fill L2 (evict-normal)
        acc.x += a * v.x; acc.y += a * v.y;
        acc.z += a * v.z; acc.w += a * v.w;
    }

    __shared__ float4 s[16][16];
    s[row][lane] = acc;
    __syncthreads();
    for (int str = 8; str >= 1; str >>= 1) {
        if (row < str) {
            float4 o = s[row + str][lane];
            float4 m = s[row][lane];
            m.x += o.x; m.y += o.y; m.z += o.z; m.w += o.w;
            s[row][lane] = m;
        }
        __syncthreads();
    }
    if (row == 0) {
        ((float4*)(g_kp + (size_t)blk * Tn))[lane] = s[0][lane];
    }
}

// ---------------------------------------------------------------------------
// Kernel 2: reduce partials -> k[b]; scores = k Wc k^T; softmax -> g_att
// grid = B (64 blocks), 64 threads
// ---------------------------------------------------------------------------
__global__ void k_scores(const float* __restrict__ Wc) {
    int b   = blockIdx.x;
    int tid = threadIdx.x;                             // 0..63

    __shared__ float ks[Cn][Tn];
    __shared__ float kW[Cn][Tn];
    __shared__ float sc[Cn][Cn];

    for (int idx = tid; idx < Cn * Tn; idx += 64) {
        int c = idx / Tn, t = idx % Tn;
        const float* p = g_kp + (((size_t)(b * Cn + c)) * CH) * Tn + t;
        float acc = 0.f;
        #pragma unroll
        for (int h = 0; h < CH; h++) acc += p[h * Tn];
        ks[c][t] = acc;
    }
    __syncthreads();

    int s = tid;
    #pragma unroll
    for (int c = 0; c < Cn; c++) {
        float acc = 0.f;
        #pragma unroll 8
        for (int t = 0; t < Tn; t++)
            acc += ks[c][t] * __ldg(Wc + t * Tn + s);
        kW[c][s] = acc;
    }
    __syncthreads();

    int c = tid >> 3, d = tid & 7;
    float sco = 0.f;
    #pragma unroll 8
    for (int ss = 0; ss < Tn; ss++)
        sco += kW[c][ss] * ks[d][ss];
    sc[c][d] = sco;
    __syncthreads();

    float m = -1e30f;
    #pragma unroll
    for (int j = 0; j < Cn; j++) m = fmaxf(m, sc[c][j]);
    float den = 0.f;
    #pragma unroll
    for (int j = 0; j < Cn; j++) den += expf(sc[c][j] - m);
    g_att[b * Cn * Cn + tid] = expf(sco - m) / den;
}

// ---------------------------------------------------------------------------
// Kernel 3: out[b,c,n,t] = sum_d att[b,c,d] * x[b,d,n,t]
// grid = B*128 blocks, 256 threads; REVERSED traversal: first CTAs touch the
// x-tail that k_reduce just left in L2. Reads evict-first, writes streaming.
// ---------------------------------------------------------------------------
__global__ void __launch_bounds__(256) k_agg(const float* __restrict__ x,
                                             float* __restrict__ out) {
    int b  = (Bn - 1) - (blockIdx.x >> 7);             // reversed batch order
    int pb = 127 - (blockIdx.x & 127);                 // reversed chunk order
    int p  = pb * 256 + threadIdx.x;                   // float4 pos in plane

    __shared__ float att[Cn * Cn];
    if (threadIdx.x < Cn * Cn)
        att[threadIdx.x] = g_att[b * Cn * Cn + threadIdx.x];
    __syncthreads();

    const float4* __restrict__ xp =
        (const float4*)x + (size_t)b * Cn * PLANE4 + p;
    float4* __restrict__ op =
        (float4*)out + (size_t)b * Cn * PLANE4 + p;

    float4 xv[Cn];
    #pragma unroll
    for (int d = 0; d < Cn; d++)
        xv[d] = __ldcs(xp + (size_t)d * PLANE4);       // single use: evict-first

    #pragma unroll
    for (int c = 0; c < Cn; c++) {
        float4 acc = make_float4(0.f, 0.f, 0.f, 0.f);
        #pragma unroll
        for (int d = 0; d < Cn; d++) {
            float a = att[c * Cn + d];
            acc.x += a * xv[d].x; acc.y += a * xv[d].y;
            acc.z += a * xv[d].z; acc.w += a * xv[d].w;
        }
        __stcs(op + (size_t)c * PLANE4, acc);
    }
}

// ---------------------------------------------------------------------------
extern "C" void kernel_launch(void* const* d_in, const int* in_sizes, int n_in,
                              void* d_out, int out_size) {
    const float* x     = (const float*)d_in[0];
    const float* Wc    = (const float*)d_in[1];
    const float* alpha = (const float*)d_in[2];
    float* out         = (float*)d_out;

    k_reduce<<<Bn * Cn * CH, 256>>>(x, alpha);
    k_scores<<<Bn, 64>>>(Wc);
    k_agg<<<Bn * 128, 256>>>(x, out);
}

// round 10
// speedup vs baseline: 1.0634x; 1.0273x over previous
#include <cuda_runtime.h>

#define Bn 64
#define Cn 8
#define Nn 2048
#define Tn 64
#define CH 8                    // i-chunks per (b,c) plane in k_reduce
#define PLANE4 (Nn * Tn / 4)    // 32768 float4 per (b,c) plane

// Scratch (no allocations allowed)
__device__ float g_kp[Bn * Cn * CH * Tn];  // partial k sums, 1 MB
__device__ float g_att[Bn * Cn * Cn];      // 4096 floats

// ---------------------------------------------------------------------------
// Kernel 1: partial k: g_kp[bc][ch][t] = sum_{i in chunk ch} alpha[i]*x[b,c,i,t]
// grid = B*C*CH = 4096 blocks, 256 threads: 16 t4-lanes x 16 i-rows. (unchanged)
// ---------------------------------------------------------------------------
__global__ void __launch_bounds__(256) k_reduce(const float* __restrict__ x,
                                                const float* __restrict__ alpha) {
    int blk = blockIdx.x;                  // 0..4095
    int bc  = blk >> 3;                    // (b,c) plane, ascending
    int ch  = blk & (CH - 1);
    int i0  = ch * (Nn / CH);              // 256-row chunk base

    const float4* __restrict__ xp =
        (const float4*)x + (size_t)bc * PLANE4 + (size_t)i0 * (Tn / 4);
    int tid  = threadIdx.x;
    int lane = tid & 15;                   // t4 index
    int row  = tid >> 4;                   // i-row group (16)

    float4 acc = make_float4(0.f, 0.f, 0.f, 0.f);
    #pragma unroll 8
    for (int it = 0; it < (Nn / CH) / 16; it++) {      // 16 iters
        int i    = it * 16 + row;
        float a  = __ldg(alpha + i0 + i);
        float4 v = __ldcg(xp + i * (Tn / 4) + lane);
        acc.x += a * v.x; acc.y += a * v.y;
        acc.z += a * v.z; acc.w += a * v.w;
    }

    __shared__ float4 s[16][16];
    s[row][lane] = acc;
    __syncthreads();
    for (int str = 8; str >= 1; str >>= 1) {
        if (row < str) {
            float4 o = s[row + str][lane];
            float4 m = s[row][lane];
            m.x += o.x; m.y += o.y; m.z += o.z; m.w += o.w;
            s[row][lane] = m;
        }
        __syncthreads();
    }
    if (row == 0) {
        ((float4*)(g_kp + (size_t)blk * Tn))[lane] = s[0][lane];
    }
}

// ---------------------------------------------------------------------------
// Kernel 2: reduce partials -> k[b]; scores = k Wc k^T; softmax -> g_att
// grid = B (64 blocks), 256 threads (more parallelism in partial-sum + kW)
// ---------------------------------------------------------------------------
__global__ void k_scores(const float* __restrict__ Wc) {
    int b   = blockIdx.x;
    int tid = threadIdx.x;                             // 0..255

    __shared__ float ks[Cn][Tn];
    __shared__ float kW[Cn][Tn];
    __shared__ float sc[Cn][Cn];

    // sum the CH partial chunks (512 elems / 256 threads = 2 each)
    for (int idx = tid; idx < Cn * Tn; idx += 256) {
        int c = idx / Tn, t = idx % Tn;
        const float* p = g_kp + (((size_t)(b * Cn + c)) * CH) * Tn + t;
        float acc = 0.f;
        #pragma unroll
        for (int h = 0; h < CH; h++) acc += p[h * Tn];
        ks[c][t] = acc;
    }
    __syncthreads();

    // kW[c][s] = sum_t ks[c][t] * Wc[t,s]  (512 entries / 256 threads)
    for (int idx = tid; idx < Cn * Tn; idx += 256) {
        int c = idx >> 6, s = idx & 63;
        float acc = 0.f;
        #pragma unroll 8
        for (int t = 0; t < Tn; t++)
            acc += ks[c][t] * __ldg(Wc + t * Tn + s);
        kW[c][s] = acc;
    }
    __syncthreads();

    if (tid < Cn * Cn) {
        int c = tid >> 3, d = tid & 7;
        float sco = 0.f;
        #pragma unroll 8
        for (int ss = 0; ss < Tn; ss++)
            sco += kW[c][ss] * ks[d][ss];
        sc[c][d] = sco;
    }
    __syncthreads();

    if (tid < Cn * Cn) {
        int c = tid >> 3;
        float m = -1e30f;
        #pragma unroll
        for (int j = 0; j < Cn; j++) m = fmaxf(m, sc[c][j]);
        float den = 0.f;
        #pragma unroll
        for (int j = 0; j < Cn; j++) den += expf(sc[c][j] - m);
        g_att[b * Cn * Cn + tid] = expf(sc[c][tid & 7] - m) / den;
    }
}

// ---------------------------------------------------------------------------
// Kernel 3: out[b,c,n,t] = sum_d att[b,c,d] * x[b,d,n,t]
// grid = B*64 blocks, 256 threads; each thread handles TWO float4 positions
// (p, p+256): 16 front-batched streaming loads, then 16 streaming stores.
// Coarser read->write phases cut DRAM bus turnaround; more loads in flight.
// ---------------------------------------------------------------------------
__global__ void __launch_bounds__(256) k_agg(const float* __restrict__ x,
                                             float* __restrict__ out) {
    int b  = (Bn - 1) - (blockIdx.x >> 6);             // reversed batch order
    int pb = 63 - (blockIdx.x & 63);                   // reversed chunk order
    int p  = pb * 512 + threadIdx.x;                   // first float4 pos

    __shared__ float att[Cn * Cn];
    if (threadIdx.x < Cn * Cn)
        att[threadIdx.x] = g_att[b * Cn * Cn + threadIdx.x];
    __syncthreads();

    const float4* __restrict__ xp =
        (const float4*)x + (size_t)b * Cn * PLANE4 + p;
    float4* __restrict__ op =
        (float4*)out + (size_t)b * Cn * PLANE4 + p;

    // 16 independent streaming loads (2 positions x 8 channels)
    float4 xv0[Cn], xv1[Cn];
    #pragma unroll
    for (int d = 0; d < Cn; d++) {
        xv0[d] = __ldcs(xp + (size_t)d * PLANE4);
        xv1[d] = __ldcs(xp + (size_t)d * PLANE4 + 256);
    }

    #pragma unroll
    for (int c = 0; c < Cn; c++) {
        float4 a0 = make_float4(0.f, 0.f, 0.f, 0.f);
        float4 a1 = make_float4(0.f, 0.f, 0.f, 0.f);
        #pragma unroll
        for (int d = 0; d < Cn; d++) {
            float a = att[c * Cn + d];
            a0.x += a * xv0[d].x; a0.y += a * xv0[d].y;
            a0.z += a * xv0[d].z; a0.w += a * xv0[d].w;
            a1.x += a * xv1[d].x; a1.y += a * xv1[d].y;
            a1.z += a * xv1[d].z; a1.w += a * xv1[d].w;
        }
        __stcs(op + (size_t)c * PLANE4, a0);
        __stcs(op + (size_t)c * PLANE4 + 256, a1);
    }
}

// ---------------------------------------------------------------------------
extern "C" void kernel_launch(void* const* d_in, const int* in_sizes, int n_in,
                              void* d_out, int out_size) {
    const float* x     = (const float*)d_in[0];
    const float* Wc    = (const float*)d_in[1];
    const float* alpha = (const float*)d_in[2];
    float* out         = (float*)d_out;

    k_reduce<<<Bn * Cn * CH, 256>>>(x, alpha);
    k_scores<<<Bn, 256>>>(Wc);
    k_agg<<<Bn * 64, 256>>>(x, out);
}

// round 13
// speedup vs baseline: 1.0842x; 1.0195x over previous
#include <cuda_runtime.h>

#define Bn 64
#define Cn 8
#define Nn 2048
#define Tn 64
#define CH 8                    // i-chunks per (b,c) plane in k_reduce
#define PLANE4 (Nn * Tn / 4)    // 32768 float4 per (b,c) plane

// Scratch (no allocations allowed)
__device__ float g_kp[Bn * Cn * CH * Tn];  // partial k sums, 1 MB
__device__ float g_att[Bn * Cn * Cn];      // 4096 floats

// ---------------------------------------------------------------------------
// Kernel 1: partial k: g_kp[bc][ch][t] = sum_{i in chunk ch} alpha[i]*x[b,c,i,t]
// grid = B*C*CH = 4096 blocks, 256 threads: 16 t4-lanes x 16 i-rows.
// Alpha staged in smem; fully unrolled 16-load body; dual accumulators.
// ---------------------------------------------------------------------------
__global__ void __launch_bounds__(256) k_reduce(const float* __restrict__ x,
                                                const float* __restrict__ alpha) {
    int blk = blockIdx.x;                  // 0..4095
    int bc  = blk >> 3;                    // (b,c) plane
    int ch  = blk & (CH - 1);
    int i0  = ch * (Nn / CH);              // 256-row chunk base

    const float4* __restrict__ xp =
        (const float4*)x + (size_t)bc * PLANE4 + (size_t)i0 * (Tn / 4);
    int tid  = threadIdx.x;
    int lane = tid & 15;                   // t4 index
    int row  = tid >> 4;                   // i-row group (16)

    // stage the 256 alpha values for this chunk in smem (one coop load)
    __shared__ float sa[Nn / CH];
    sa[tid] = __ldg(alpha + i0 + tid);
    __syncthreads();

    // 16 i-rows per thread, fully unrolled as 8 x (2 independent streams)
    float4 acc0 = make_float4(0.f, 0.f, 0.f, 0.f);
    float4 acc1 = make_float4(0.f, 0.f, 0.f, 0.f);
    #pragma unroll
    for (int it = 0; it < 8; it++) {
        int ia = it * 32 + row;            // rows 0..255, stride-16 pair
        int ib = ia + 16;
        float  a0 = sa[ia];
        float  a1 = sa[ib];
        float4 v0 = __ldcg(xp + ia * 16 + lane);
        float4 v1 = __ldcg(xp + ib * 16 + lane);
        acc0.x += a0 * v0.x; acc0.y += a0 * v0.y;
        acc0.z += a0 * v0.z; acc0.w += a0 * v0.w;
        acc1.x += a1 * v1.x; acc1.y += a1 * v1.y;
        acc1.z += a1 * v1.z; acc1.w += a1 * v1.w;
    }
    acc0.x += acc1.x; acc0.y += acc1.y; acc0.z += acc1.z; acc0.w += acc1.w;

    __shared__ float4 s[16][16];
    s[row][lane] = acc0;
    __syncthreads();
    for (int str = 8; str >= 1; str >>= 1) {
        if (row < str) {
            float4 o = s[row + str][lane];
            float4 m = s[row][lane];
            m.x += o.x; m.y += o.y; m.z += o.z; m.w += o.w;
            s[row][lane] = m;
        }
        __syncthreads();
    }
    if (row == 0) {
        ((float4*)(g_kp + (size_t)blk * Tn))[lane] = s[0][lane];
    }
}

// ---------------------------------------------------------------------------
// Kernel 2: reduce partials -> k[b]; scores = k Wc k^T; softmax -> g_att
// grid = B (64 blocks), 256 threads
// ---------------------------------------------------------------------------
__global__ void k_scores(const float* __restrict__ Wc) {
    int b   = blockIdx.x;
    int tid = threadIdx.x;                             // 0..255

    __shared__ float ks[Cn][Tn];
    __shared__ float kW[Cn][Tn];
    __shared__ float sc[Cn][Cn];

    for (int idx = tid; idx < Cn * Tn; idx += 256) {
        int c = idx / Tn, t = idx % Tn;
        const float* p = g_kp + (((size_t)(b * Cn + c)) * CH) * Tn + t;
        float acc = 0.f;
        #pragma unroll
        for (int h = 0; h < CH; h++) acc += p[h * Tn];
        ks[c][t] = acc;
    }
    __syncthreads();

    for (int idx = tid; idx < Cn * Tn; idx += 256) {
        int c = idx >> 6, s = idx & 63;
        float acc = 0.f;
        #pragma unroll 8
        for (int t = 0; t < Tn; t++)
            acc += ks[c][t] * __ldg(Wc + t * Tn + s);
        kW[c][s] = acc;
    }
    __syncthreads();

    if (tid < Cn * Cn) {
        int c = tid >> 3, d = tid & 7;
        float sco = 0.f;
        #pragma unroll 8
        for (int ss = 0; ss < Tn; ss++)
            sco += kW[c][ss] * ks[d][ss];
        sc[c][d] = sco;
    }
    __syncthreads();

    if (tid < Cn * Cn) {
        int c = tid >> 3;
        float m = -1e30f;
        #pragma unroll
        for (int j = 0; j < Cn; j++) m = fmaxf(m, sc[c][j]);
        float den = 0.f;
        #pragma unroll
        for (int j = 0; j < Cn; j++) den += expf(sc[c][j] - m);
        g_att[b * Cn * Cn + tid] = expf(sc[c][tid & 7] - m) / den;
    }
}

// ---------------------------------------------------------------------------
// Kernel 3: out[b,c,n,t] = sum_d att[b,c,d] * x[b,d,n,t]  (unchanged from R10)
// grid = B*64 blocks, 256 threads; 2 float4 positions/thread, 16 batched loads.
// ---------------------------------------------------------------------------
__global__ void __launch_bounds__(256) k_agg(const float* __restrict__ x,
                                             float* __restrict__ out) {
    int b  = (Bn - 1) - (blockIdx.x >> 6);
    int pb = 63 - (blockIdx.x & 63);
    int p  = pb * 512 + threadIdx.x;

    __shared__ float att[Cn * Cn];
    if (threadIdx.x < Cn * Cn)
        att[threadIdx.x] = g_att[b * Cn * Cn + threadIdx.x];
    __syncthreads();

    const float4* __restrict__ xp =
        (const float4*)x + (size_t)b * Cn * PLANE4 + p;
    float4* __restrict__ op =
        (float4*)out + (size_t)b * Cn * PLANE4 + p;

    float4 xv0[Cn], xv1[Cn];
    #pragma unroll
    for (int d = 0; d < Cn; d++) {
        xv0[d] = __ldcs(xp + (size_t)d * PLANE4);
        xv1[d] = __ldcs(xp + (size_t)d * PLANE4 + 256);
    }

    #pragma unroll
    for (int c = 0; c < Cn; c++) {
        float4 a0 = make_float4(0.f, 0.f, 0.f, 0.f);
        float4 a1 = make_float4(0.f, 0.f, 0.f, 0.f);
        #pragma unroll
        for (int d = 0; d < Cn; d++) {
            float a = att[c * Cn + d];
            a0.x += a * xv0[d].x; a0.y += a * xv0[d].y;
            a0.z += a * xv0[d].z; a0.w += a * xv0[d].w;
            a1.x += a * xv1[d].x; a1.y += a * xv1[d].y;
            a1.z += a * xv1[d].z; a1.w += a * xv1[d].w;
        }
        __stcs(op + (size_t)c * PLANE4, a0);
        __stcs(op + (size_t)c * PLANE4 + 256, a1);
    }
}

// ---------------------------------------------------------------------------
extern "C" void kernel_launch(void* const* d_in, const int* in_sizes, int n_in,
                              void* d_out, int out_size) {
    const float* x     = (const float*)d_in[0];
    const float* Wc    = (const float*)d_in[1];
    const float* alpha = (const float*)d_in[2];
    float* out         = (float*)d_out;

    k_reduce<<<Bn * Cn * CH, 256>>>(x, alpha);
    k_scores<<<Bn, 256>>>(Wc);
    k_agg<<<Bn * 64, 256>>>(x, out);
}